// round 6
// baseline (speedup 1.0000x reference)
#include <cuda_runtime.h>

#define HH 512
#define WW 512
#define BC 6
#define NPIX (HH * WW)

// ---- static device scratch (no runtime allocation allowed) ----
// State recycling: counters start zero (CUDA zero-init) and every replay
// re-zeros them at a point ordered before their next use:
//   g_sum/g_sumsq : zeroed in k_sobel (before k_iter3's atomics)
//   g_gmax        : zeroed in k_norm  (after its last reader)
__device__ float g_gmag[BC * NPIX];
__device__ float g_xnA[BC * NPIX];
__device__ float g_ynA[BC * NPIX];
__device__ float g_xnB[BC * NPIX];
__device__ float g_ynB[BC * NPIX];
__device__ int    g_gmax[BC];
__device__ double g_sum[BC];
__device__ double g_sumsq[BC];

__device__ __forceinline__ int refl(int i, int n) {
    if (i < 0) i = -i;
    if (i >= n) i = 2 * (n - 1) - i;
    return i;
}

__device__ __forceinline__ float tanh_fast(float x) {
    float y;
    asm("tanh.approx.f32 %0, %1;" : "=f"(y) : "f"(x));
    return y;
}

// Branchless Cephes-style atan, max err ~2e-7 rad.
__device__ __forceinline__ float atan_fast(float x) {
    float ax = fabsf(x);
    bool big = ax > 2.414213562f;     // tan(3pi/8)
    bool mid = ax > 0.4142135624f;    // tan(pi/8)
    float num = big ? -1.0f : ax - 1.0f;
    float den = big ? ax : ax + 1.0f;
    float r = mid ? __fdividef(num, den) : ax;
    float base = big ? 1.57079632679f : (mid ? 0.78539816340f : 0.0f);
    float z = r * r;
    float p = fmaf(fmaf(fmaf(8.05374449538e-2f, z, -1.38776856032e-1f), z,
                        1.99777106478e-1f), z, -3.33329491539e-1f);
    float res = base + fmaf(p * z, r, r);
    return copysignf(res, x);
}

// -------------------- Sobel + rotate + gmag max --------------------
__global__ void k_sobel(const float* __restrict__ img) {
    int c = blockIdx.z;
    const float* p = img + c * NPIX;
    int x = blockIdx.x * 32 + threadIdx.x;
    int y = blockIdx.y * 8 + threadIdx.y;
    int tid = threadIdx.y * 32 + threadIdx.x;

    if (blockIdx.x == 0 && blockIdx.y == 0 && tid == 0) {
        g_sum[c] = 0.0;
        g_sumsq[c] = 0.0;
    }

    float a[3][3];
#pragma unroll
    for (int j = 0; j < 3; j++)
#pragma unroll
        for (int i = 0; i < 3; i++) {
            int yy = y + j - 1, xx = x + i - 1;
            a[j][i] = ((unsigned)yy < HH && (unsigned)xx < WW) ? p[yy * WW + xx] : 0.f;
        }
    float gx = (a[0][2] - a[0][0]) + 2.f * (a[1][2] - a[1][0]) + (a[2][2] - a[2][0]);
    float gy = (a[2][0] - a[0][0]) + 2.f * (a[2][1] - a[0][1]) + (a[2][2] - a[0][2]);
    // uniform input scale (imgmax) dropped: results are scale-invariant
    gx = fmaxf(gx, 1e-12f);
    gy = fmaxf(gy, 1e-12f);

    float gm = sqrtf(fmaf(gx, gx, gy * gy));
    float invg = 1.0f / gm;
    float x0 = gx * invg, y0 = gy * invg;
    const float ct = -4.3711388e-08f, st = 1.0f;  // fp32 cos/sin(pi/2)
    float xn = x0 * ct - y0 * st;
    float yn = y0 * ct + x0 * st;

    int o = c * NPIX + y * WW + x;
    g_gmag[o] = gm;
    g_xnA[o]  = xn;
    g_ynA[o]  = yn;

    __shared__ float sm[8];
    int lane = tid & 31, warp = tid >> 5;
    float m = gm;
#pragma unroll
    for (int off = 16; off; off >>= 1) m = fmaxf(m, __shfl_xor_sync(0xffffffffu, m, off));
    if (lane == 0) sm[warp] = m;
    __syncthreads();
    if (tid == 0) {
#pragma unroll
        for (int i = 1; i < 8; i++) m = fmaxf(m, sm[i]);
        atomicMax(&g_gmax[c], __float_as_int(m));
    }
}

// -------------------- shared tile loader for ETF iterations --------------------
__device__ __forceinline__ void load_tile(
    float4 (*sN)[36], float (*sG)[36],
    const float* __restrict__ gm, const float* __restrict__ xi,
    const float* __restrict__ yi, float ginv, int bx0, int by0, int tid) {
    bool interior = (bx0 >= 0) && (by0 >= 0) && (bx0 + 36 <= WW) && (by0 + 36 <= HH);
    if (interior) {
        for (int i = tid; i < 36 * 36; i += 256) {
            int ly = i / 36, lx = i - ly * 36;
            int o = (by0 + ly) * WW + bx0 + lx;
            float gn = gm[o] * ginv;
            float xv = xi[o], yv = yi[o];
            sN[ly][lx] = make_float4(xv, yv, gn * xv, gn * yv);
            sG[ly][lx] = gn;
        }
    } else {
        for (int i = tid; i < 36 * 36; i += 256) {
            int ly = i / 36, lx = i - ly * 36;
            int o = refl(by0 + ly, HH) * WW + refl(bx0 + lx, WW);
            float gn = gm[o] * ginv;
            float xv = xi[o], yv = yi[o];
            sN[ly][lx] = make_float4(xv, yv, gn * xv, gn * yv);
            sG[ly][lx] = gn;
        }
    }
}

// core 5x5 weighted accumulation for 4 consecutive rows per thread
__device__ __forceinline__ void etf_core(
    float4 (*sN)[36], float (*sG)[36], int tx, int row0,
    float* xr, float* yr) {
    float gc[4], xc[4], yc[4];
#pragma unroll
    for (int k = 0; k < 4; k++) {
        float4 v = sN[row0 + 2 + k][tx + 2];
        gc[k] = sG[row0 + 2 + k][tx + 2];
        xc[k] = v.x; yc[k] = v.y;
        xr[k] = 0.f; yr[k] = 0.f;
    }
#pragma unroll
    for (int r = 0; r < 8; r++) {
        float4 n5[5];
        float  g5[5];
#pragma unroll
        for (int dx = 0; dx < 5; dx++) {
            n5[dx] = sN[row0 + r][tx + dx];
            g5[dx] = sG[row0 + r][tx + dx];
        }
#pragma unroll
        for (int k = 0; k < 4; k++) {
            if (r >= k && r <= k + 4) {
#pragma unroll
                for (int dx = 0; dx < 5; dx++) {
                    float th  = tanh_fast(g5[dx] - gc[k]);
                    float dot = fmaf(xc[k], n5[dx].x, yc[k] * n5[dx].y);
                    float u   = fmaf(th, dot, dot);      // (1+tanh)*dot
                    xr[k] = fmaf(n5[dx].z, u, xr[k]);
                    yr[k] = fmaf(n5[dx].w, u, yr[k]);
                }
            }
        }
    }
}

// -------------------- ETF iterations 1 & 2 --------------------
__global__ void __launch_bounds__(256, 6) k_iter(int sel) {
    __shared__ float4 sN[36][36];
    __shared__ float  sG[36][36];

    int c = blockIdx.z;
    const float* gm = g_gmag + c * NPIX;
    const float* xi = (sel ? g_xnB : g_xnA) + c * NPIX;
    const float* yi = (sel ? g_ynB : g_ynA) + c * NPIX;
    float* xo = (sel ? g_xnA : g_xnB) + c * NPIX;
    float* yo = (sel ? g_ynA : g_ynB) + c * NPIX;

    float ginv = 1.0f / __int_as_float(g_gmax[c]);
    int bx0 = blockIdx.x * 32 - 2;
    int by0 = blockIdx.y * 32 - 2;
    int tid = threadIdx.y * 32 + threadIdx.x;

    load_tile(sN, sG, gm, xi, yi, ginv, bx0, by0, tid);
    __syncthreads();

    int tx = threadIdx.x;
    int row0 = threadIdx.y * 4;
    int px = blockIdx.x * 32 + tx;
    float xr[4], yr[4];
    etf_core(sN, sG, tx, row0, xr, yr);

#pragma unroll
    for (int k = 0; k < 4; k++) {
        float invm = rsqrtf(fmaf(xr[k], xr[k], yr[k] * yr[k]));
        int o = (blockIdx.y * 32 + row0 + k) * WW + px;
        xo[o] = xr[k] * invm;
        yo[o] = yr[k] * invm;
    }
}

// -------------------- ETF iteration 3 fused with angle + stats --------------------
// Reduction: fp32 warp-level shuffles only (|a|<=90, 128-value partials are
// accurate to ~1e-6 rel), then one fp64 no-return atomic per warp per counter.
// No smem stage, no trailing __syncthreads.
__global__ void __launch_bounds__(256, 6) k_iter3(float* __restrict__ out) {
    __shared__ float4 sN[36][36];
    __shared__ float  sG[36][36];

    int c = blockIdx.z;
    const float* gm = g_gmag + c * NPIX;
    const float* xi = g_xnA + c * NPIX;   // iter1: A->B, iter2: B->A, iter3 reads A
    const float* yi = g_ynA + c * NPIX;

    float ginv = 1.0f / __int_as_float(g_gmax[c]);
    int bx0 = blockIdx.x * 32 - 2;
    int by0 = blockIdx.y * 32 - 2;
    int tid = threadIdx.y * 32 + threadIdx.x;

    load_tile(sN, sG, gm, xi, yi, ginv, bx0, by0, tid);
    __syncthreads();

    int tx = threadIdx.x;
    int row0 = threadIdx.y * 4;
    int px = blockIdx.x * 32 + tx;
    float xr[4], yr[4];
    etf_core(sN, sG, tx, row0, xr, yr);

    float s = 0.f, s2 = 0.f;
#pragma unroll
    for (int k = 0; k < 4; k++) {
        // normalization cancels inside atan(-y/x); divide directly
        float t = __fdividef(-yr[k], xr[k]);
        float a = atan_fast(t) * 57.2957795131f;  // 180/pi
        int o = c * NPIX + (blockIdx.y * 32 + row0 + k) * WW + px;
        out[o] = a;
        s += a;
        s2 = fmaf(a, a, s2);
    }

#pragma unroll
    for (int off = 16; off; off >>= 1) {
        s  += __shfl_xor_sync(0xffffffffu, s, off);
        s2 += __shfl_xor_sync(0xffffffffu, s2, off);
    }
    if ((tid & 31) == 0) {
        atomicAdd(&g_sum[c], (double)s);     // return unused -> REDG
        atomicAdd(&g_sumsq[c], (double)s2);
    }
}

// -------------------- normalize + recycle state --------------------
__global__ void k_norm(float* __restrict__ out) {
    __shared__ float smu, sinv;
    int c = blockIdx.y;
    if (threadIdx.x == 0) {
        double mean = g_sum[c] / (double)NPIX;
        double var  = g_sumsq[c] / (double)NPIX - mean * mean;
        smu  = (float)mean;
        sinv = (float)(1.0 / sqrt(var + 1e-5));
        if (blockIdx.x == 0) g_gmax[c] = 0;   // recycle for next replay
    }
    __syncthreads();
    int o = c * NPIX + blockIdx.x * blockDim.x + threadIdx.x;
    out[o] = (out[o] - smu) * sinv;
}

extern "C" void kernel_launch(void* const* d_in, const int* in_sizes, int n_in,
                              void* d_out, int out_size) {
    const float* img = (const float*)d_in[0];
    float* out = (float*)d_out;

    k_sobel<<<dim3(WW / 32, HH / 8, BC), dim3(32, 8)>>>(img);
    k_iter<<<dim3(16, 16, BC), dim3(32, 8)>>>(0);   // A -> B
    k_iter<<<dim3(16, 16, BC), dim3(32, 8)>>>(1);   // B -> A
    k_iter3<<<dim3(16, 16, BC), dim3(32, 8)>>>(out);// A -> out (+stats)
    k_norm<<<dim3(NPIX / 256, BC), 256>>>(out);
}

// round 7
// speedup vs baseline: 1.4513x; 1.4513x over previous
#include <cuda_runtime.h>

#define HH 512
#define WW 512
#define BC 6
#define NPIX (HH * WW)

// ---- static device scratch (no runtime allocation allowed) ----
// State recycling: counters start zero (CUDA zero-init) and every replay
// re-zeros them at a point ordered before their next use:
//   g_sum/g_sumsq : zeroed in k_sobel (before k_iter3's atomics)
//   g_gmax        : zeroed in k_norm  (after its last reader)
__device__ float g_gmag[BC * NPIX];
__device__ float g_xnA[BC * NPIX];
__device__ float g_ynA[BC * NPIX];
__device__ float g_xnB[BC * NPIX];
__device__ float g_ynB[BC * NPIX];
__device__ int    g_gmax[BC];
__device__ double g_sum[BC];
__device__ double g_sumsq[BC];

__device__ __forceinline__ int refl(int i, int n) {
    if (i < 0) i = -i;
    if (i >= n) i = 2 * (n - 1) - i;
    return i;
}

__device__ __forceinline__ float tanh_fast(float x) {
    float y;
    asm("tanh.approx.f32 %0, %1;" : "=f"(y) : "f"(x));
    return y;
}

// Branchless Cephes-style atan, max err ~2e-7 rad.
__device__ __forceinline__ float atan_fast(float x) {
    float ax = fabsf(x);
    bool big = ax > 2.414213562f;     // tan(3pi/8)
    bool mid = ax > 0.4142135624f;    // tan(pi/8)
    float num = big ? -1.0f : ax - 1.0f;
    float den = big ? ax : ax + 1.0f;
    float r = mid ? __fdividef(num, den) : ax;
    float base = big ? 1.57079632679f : (mid ? 0.78539816340f : 0.0f);
    float z = r * r;
    float p = fmaf(fmaf(fmaf(8.05374449538e-2f, z, -1.38776856032e-1f), z,
                        1.99777106478e-1f), z, -3.33329491539e-1f);
    float res = base + fmaf(p * z, r, r);
    return copysignf(res, x);
}

// -------------------- Sobel + rotate + gmag max --------------------
__global__ void k_sobel(const float* __restrict__ img) {
    int c = blockIdx.z;
    const float* p = img + c * NPIX;
    int x = blockIdx.x * 32 + threadIdx.x;
    int y = blockIdx.y * 8 + threadIdx.y;
    int tid = threadIdx.y * 32 + threadIdx.x;

    if (blockIdx.x == 0 && blockIdx.y == 0 && tid == 0) {
        g_sum[c] = 0.0;
        g_sumsq[c] = 0.0;
    }

    float a[3][3];
#pragma unroll
    for (int j = 0; j < 3; j++)
#pragma unroll
        for (int i = 0; i < 3; i++) {
            int yy = y + j - 1, xx = x + i - 1;
            a[j][i] = ((unsigned)yy < HH && (unsigned)xx < WW) ? p[yy * WW + xx] : 0.f;
        }
    float gx = (a[0][2] - a[0][0]) + 2.f * (a[1][2] - a[1][0]) + (a[2][2] - a[2][0]);
    float gy = (a[2][0] - a[0][0]) + 2.f * (a[2][1] - a[0][1]) + (a[2][2] - a[0][2]);
    // uniform input scale (imgmax) dropped: results are scale-invariant
    gx = fmaxf(gx, 1e-12f);
    gy = fmaxf(gy, 1e-12f);

    float gm = sqrtf(fmaf(gx, gx, gy * gy));
    float invg = 1.0f / gm;
    float x0 = gx * invg, y0 = gy * invg;
    const float ct = -4.3711388e-08f, st = 1.0f;  // fp32 cos/sin(pi/2)
    float xn = x0 * ct - y0 * st;
    float yn = y0 * ct + x0 * st;

    int o = c * NPIX + y * WW + x;
    g_gmag[o] = gm;
    g_xnA[o]  = xn;
    g_ynA[o]  = yn;

    __shared__ float sm[8];
    int lane = tid & 31, warp = tid >> 5;
    float m = gm;
#pragma unroll
    for (int off = 16; off; off >>= 1) m = fmaxf(m, __shfl_xor_sync(0xffffffffu, m, off));
    if (lane == 0) sm[warp] = m;
    __syncthreads();
    if (tid == 0) {
#pragma unroll
        for (int i = 1; i < 8; i++) m = fmaxf(m, sm[i]);
        atomicMax(&g_gmax[c], __float_as_int(m));
    }
}

// -------------------- shared tile loader for ETF iterations --------------------
__device__ __forceinline__ void load_tile(
    float4 (*sN)[36], float (*sG)[36],
    const float* __restrict__ gm, const float* __restrict__ xi,
    const float* __restrict__ yi, float ginv, int bx0, int by0, int tid) {
    bool interior = (bx0 >= 0) && (by0 >= 0) && (bx0 + 36 <= WW) && (by0 + 36 <= HH);
    if (interior) {
        for (int i = tid; i < 36 * 36; i += 256) {
            int ly = i / 36, lx = i - ly * 36;
            int o = (by0 + ly) * WW + bx0 + lx;
            float gn = gm[o] * ginv;
            float xv = xi[o], yv = yi[o];
            sN[ly][lx] = make_float4(xv, yv, gn * xv, gn * yv);
            sG[ly][lx] = gn;
        }
    } else {
        for (int i = tid; i < 36 * 36; i += 256) {
            int ly = i / 36, lx = i - ly * 36;
            int o = refl(by0 + ly, HH) * WW + refl(bx0 + lx, WW);
            float gn = gm[o] * ginv;
            float xv = xi[o], yv = yi[o];
            sN[ly][lx] = make_float4(xv, yv, gn * xv, gn * yv);
            sG[ly][lx] = gn;
        }
    }
}

// core 5x5 weighted accumulation for 4 consecutive rows per thread
__device__ __forceinline__ void etf_core(
    float4 (*sN)[36], float (*sG)[36], int tx, int row0,
    float* xr, float* yr) {
    float gc[4], xc[4], yc[4];
#pragma unroll
    for (int k = 0; k < 4; k++) {
        float4 v = sN[row0 + 2 + k][tx + 2];
        gc[k] = sG[row0 + 2 + k][tx + 2];
        xc[k] = v.x; yc[k] = v.y;
        xr[k] = 0.f; yr[k] = 0.f;
    }
#pragma unroll
    for (int r = 0; r < 8; r++) {
        float4 n5[5];
        float  g5[5];
#pragma unroll
        for (int dx = 0; dx < 5; dx++) {
            n5[dx] = sN[row0 + r][tx + dx];
            g5[dx] = sG[row0 + r][tx + dx];
        }
#pragma unroll
        for (int k = 0; k < 4; k++) {
            if (r >= k && r <= k + 4) {
#pragma unroll
                for (int dx = 0; dx < 5; dx++) {
                    float th  = tanh_fast(g5[dx] - gc[k]);
                    float dot = fmaf(xc[k], n5[dx].x, yc[k] * n5[dx].y);
                    float u   = fmaf(th, dot, dot);      // (1+tanh)*dot
                    xr[k] = fmaf(n5[dx].z, u, xr[k]);
                    yr[k] = fmaf(n5[dx].w, u, yr[k]);
                }
            }
        }
    }
}

// -------------------- ETF iterations 1 & 2 --------------------
// NOTE: no min-blocks clause. Capping to 6 blocks/SM (40 regs) in round 6
// caused spills in the unrolled core (L1% 38->53, +6us). 48 regs / occ~52%
// is the sweet spot here.
__global__ void __launch_bounds__(256) k_iter(int sel) {
    __shared__ float4 sN[36][36];
    __shared__ float  sG[36][36];

    int c = blockIdx.z;
    const float* gm = g_gmag + c * NPIX;
    const float* xi = (sel ? g_xnB : g_xnA) + c * NPIX;
    const float* yi = (sel ? g_ynB : g_ynA) + c * NPIX;
    float* xo = (sel ? g_xnA : g_xnB) + c * NPIX;
    float* yo = (sel ? g_ynA : g_ynB) + c * NPIX;

    float ginv = 1.0f / __int_as_float(g_gmax[c]);
    int bx0 = blockIdx.x * 32 - 2;
    int by0 = blockIdx.y * 32 - 2;
    int tid = threadIdx.y * 32 + threadIdx.x;

    load_tile(sN, sG, gm, xi, yi, ginv, bx0, by0, tid);
    __syncthreads();

    int tx = threadIdx.x;
    int row0 = threadIdx.y * 4;
    int px = blockIdx.x * 32 + tx;
    float xr[4], yr[4];
    etf_core(sN, sG, tx, row0, xr, yr);

#pragma unroll
    for (int k = 0; k < 4; k++) {
        float invm = rsqrtf(fmaf(xr[k], xr[k], yr[k] * yr[k]));
        int o = (blockIdx.y * 32 + row0 + k) * WW + px;
        xo[o] = xr[k] * invm;
        yo[o] = yr[k] * invm;
    }
}

// -------------------- ETF iteration 3 fused with angle + stats --------------------
// Reduction: fp32 warp-level shuffles only (|a|<=90, 128-value partials are
// accurate to ~1e-6 rel), then one fp64 no-return atomic per warp per counter.
// No smem stage, no trailing __syncthreads.
__global__ void __launch_bounds__(256) k_iter3(float* __restrict__ out) {
    __shared__ float4 sN[36][36];
    __shared__ float  sG[36][36];

    int c = blockIdx.z;
    const float* gm = g_gmag + c * NPIX;
    const float* xi = g_xnA + c * NPIX;   // iter1: A->B, iter2: B->A, iter3 reads A
    const float* yi = g_ynA + c * NPIX;

    float ginv = 1.0f / __int_as_float(g_gmax[c]);
    int bx0 = blockIdx.x * 32 - 2;
    int by0 = blockIdx.y * 32 - 2;
    int tid = threadIdx.y * 32 + threadIdx.x;

    load_tile(sN, sG, gm, xi, yi, ginv, bx0, by0, tid);
    __syncthreads();

    int tx = threadIdx.x;
    int row0 = threadIdx.y * 4;
    int px = blockIdx.x * 32 + tx;
    float xr[4], yr[4];
    etf_core(sN, sG, tx, row0, xr, yr);

    float s = 0.f, s2 = 0.f;
#pragma unroll
    for (int k = 0; k < 4; k++) {
        // normalization cancels inside atan(-y/x); divide directly
        float t = __fdividef(-yr[k], xr[k]);
        float a = atan_fast(t) * 57.2957795131f;  // 180/pi
        int o = c * NPIX + (blockIdx.y * 32 + row0 + k) * WW + px;
        out[o] = a;
        s += a;
        s2 = fmaf(a, a, s2);
    }

#pragma unroll
    for (int off = 16; off; off >>= 1) {
        s  += __shfl_xor_sync(0xffffffffu, s, off);
        s2 += __shfl_xor_sync(0xffffffffu, s2, off);
    }
    if ((tid & 31) == 0) {
        atomicAdd(&g_sum[c], (double)s);     // return unused -> REDG
        atomicAdd(&g_sumsq[c], (double)s2);
    }
}

// -------------------- normalize + recycle state --------------------
__global__ void k_norm(float* __restrict__ out) {
    __shared__ float smu, sinv;
    int c = blockIdx.y;
    if (threadIdx.x == 0) {
        double mean = g_sum[c] / (double)NPIX;
        double var  = g_sumsq[c] / (double)NPIX - mean * mean;
        smu  = (float)mean;
        sinv = (float)(1.0 / sqrt(var + 1e-5));
        if (blockIdx.x == 0) g_gmax[c] = 0;   // recycle for next replay
    }
    __syncthreads();
    int o = c * NPIX + blockIdx.x * blockDim.x + threadIdx.x;
    out[o] = (out[o] - smu) * sinv;
}

extern "C" void kernel_launch(void* const* d_in, const int* in_sizes, int n_in,
                              void* d_out, int out_size) {
    const float* img = (const float*)d_in[0];
    float* out = (float*)d_out;

    k_sobel<<<dim3(WW / 32, HH / 8, BC), dim3(32, 8)>>>(img);
    k_iter<<<dim3(16, 16, BC), dim3(32, 8)>>>(0);   // A -> B
    k_iter<<<dim3(16, 16, BC), dim3(32, 8)>>>(1);   // B -> A
    k_iter3<<<dim3(16, 16, BC), dim3(32, 8)>>>(out);// A -> out (+stats)
    k_norm<<<dim3(NPIX / 256, BC), 256>>>(out);
}

// round 8
// speedup vs baseline: 1.5686x; 1.0808x over previous
#include <cuda_runtime.h>

#define HH 512
#define WW 512
#define BC 6
#define NPIX (HH * WW)

// tile geometry: 32 wide x 16 tall outputs, 128 threads (32x4), 4 rows/thread
#define TW 32
#define TH 16
#define HW 36   // TW + 4
#define HHALO 20 // TH + 4

// ---- static device scratch (no runtime allocation allowed) ----
// State recycling: counters start zero (CUDA zero-init) and every replay
// re-zeros them at a point ordered before their next use:
//   g_sum/g_sumsq : zeroed in k_sobel (before k_iter3's atomics)
//   g_gmax        : zeroed in k_norm  (after its last reader)
__device__ float g_gmag[BC * NPIX];
__device__ float g_xnA[BC * NPIX];
__device__ float g_ynA[BC * NPIX];
__device__ float g_xnB[BC * NPIX];
__device__ float g_ynB[BC * NPIX];
__device__ int    g_gmax[BC];
__device__ double g_sum[BC];
__device__ double g_sumsq[BC];

__device__ __forceinline__ int refl(int i, int n) {
    if (i < 0) i = -i;
    if (i >= n) i = 2 * (n - 1) - i;
    return i;
}

__device__ __forceinline__ float tanh_fast(float x) {
    float y;
    asm("tanh.approx.f32 %0, %1;" : "=f"(y) : "f"(x));
    return y;
}

// Branchless Cephes-style atan, max err ~2e-7 rad.
__device__ __forceinline__ float atan_fast(float x) {
    float ax = fabsf(x);
    bool big = ax > 2.414213562f;     // tan(3pi/8)
    bool mid = ax > 0.4142135624f;    // tan(pi/8)
    float num = big ? -1.0f : ax - 1.0f;
    float den = big ? ax : ax + 1.0f;
    float r = mid ? __fdividef(num, den) : ax;
    float base = big ? 1.57079632679f : (mid ? 0.78539816340f : 0.0f);
    float z = r * r;
    float p = fmaf(fmaf(fmaf(8.05374449538e-2f, z, -1.38776856032e-1f), z,
                        1.99777106478e-1f), z, -3.33329491539e-1f);
    float res = base + fmaf(p * z, r, r);
    return copysignf(res, x);
}

// -------------------- Sobel + rotate + gmag max --------------------
__global__ void k_sobel(const float* __restrict__ img) {
    int c = blockIdx.z;
    const float* p = img + c * NPIX;
    int x = blockIdx.x * 32 + threadIdx.x;
    int y = blockIdx.y * 8 + threadIdx.y;
    int tid = threadIdx.y * 32 + threadIdx.x;

    if (blockIdx.x == 0 && blockIdx.y == 0 && tid == 0) {
        g_sum[c] = 0.0;
        g_sumsq[c] = 0.0;
    }

    float a[3][3];
#pragma unroll
    for (int j = 0; j < 3; j++)
#pragma unroll
        for (int i = 0; i < 3; i++) {
            int yy = y + j - 1, xx = x + i - 1;
            a[j][i] = ((unsigned)yy < HH && (unsigned)xx < WW) ? p[yy * WW + xx] : 0.f;
        }
    float gx = (a[0][2] - a[0][0]) + 2.f * (a[1][2] - a[1][0]) + (a[2][2] - a[2][0]);
    float gy = (a[2][0] - a[0][0]) + 2.f * (a[2][1] - a[0][1]) + (a[2][2] - a[0][2]);
    // uniform input scale (imgmax) dropped: results are scale-invariant
    gx = fmaxf(gx, 1e-12f);
    gy = fmaxf(gy, 1e-12f);

    float gm = sqrtf(fmaf(gx, gx, gy * gy));
    float invg = 1.0f / gm;
    float x0 = gx * invg, y0 = gy * invg;
    const float ct = -4.3711388e-08f, st = 1.0f;  // fp32 cos/sin(pi/2)
    float xn = x0 * ct - y0 * st;
    float yn = y0 * ct + x0 * st;

    int o = c * NPIX + y * WW + x;
    g_gmag[o] = gm;
    g_xnA[o]  = xn;
    g_ynA[o]  = yn;

    __shared__ float sm[8];
    int lane = tid & 31, warp = tid >> 5;
    float m = gm;
#pragma unroll
    for (int off = 16; off; off >>= 1) m = fmaxf(m, __shfl_xor_sync(0xffffffffu, m, off));
    if (lane == 0) sm[warp] = m;
    __syncthreads();
    if (tid == 0) {
#pragma unroll
        for (int i = 1; i < 8; i++) m = fmaxf(m, sm[i]);
        atomicMax(&g_gmax[c], __float_as_int(m));
    }
}

// -------------------- shared tile loader for ETF iterations --------------------
__device__ __forceinline__ void load_tile(
    float4 (*sN)[HW], float (*sG)[HW],
    const float* __restrict__ gm, const float* __restrict__ xi,
    const float* __restrict__ yi, float ginv, int bx0, int by0, int tid) {
    bool interior = (bx0 >= 0) && (by0 >= 0) && (bx0 + HW <= WW) && (by0 + HHALO <= HH);
    if (interior) {
        for (int i = tid; i < HHALO * HW; i += 128) {
            int ly = i / HW, lx = i - ly * HW;
            int o = (by0 + ly) * WW + bx0 + lx;
            float gn = gm[o] * ginv;
            float xv = xi[o], yv = yi[o];
            sN[ly][lx] = make_float4(xv, yv, gn * xv, gn * yv);
            sG[ly][lx] = gn;
        }
    } else {
        for (int i = tid; i < HHALO * HW; i += 128) {
            int ly = i / HW, lx = i - ly * HW;
            int o = refl(by0 + ly, HH) * WW + refl(bx0 + lx, WW);
            float gn = gm[o] * ginv;
            float xv = xi[o], yv = yi[o];
            sN[ly][lx] = make_float4(xv, yv, gn * xv, gn * yv);
            sG[ly][lx] = gn;
        }
    }
}

// core 5x5 weighted accumulation for 4 consecutive rows per thread
__device__ __forceinline__ void etf_core(
    float4 (*sN)[HW], float (*sG)[HW], int tx, int row0,
    float* xr, float* yr) {
    float gc[4], xc[4], yc[4];
#pragma unroll
    for (int k = 0; k < 4; k++) {
        float4 v = sN[row0 + 2 + k][tx + 2];
        gc[k] = sG[row0 + 2 + k][tx + 2];
        xc[k] = v.x; yc[k] = v.y;
        xr[k] = 0.f; yr[k] = 0.f;
    }
#pragma unroll
    for (int r = 0; r < 8; r++) {
        float4 n5[5];
        float  g5[5];
#pragma unroll
        for (int dx = 0; dx < 5; dx++) {
            n5[dx] = sN[row0 + r][tx + dx];
            g5[dx] = sG[row0 + r][tx + dx];
        }
#pragma unroll
        for (int k = 0; k < 4; k++) {
            if (r >= k && r <= k + 4) {
#pragma unroll
                for (int dx = 0; dx < 5; dx++) {
                    float th  = tanh_fast(g5[dx] - gc[k]);
                    float dot = fmaf(xc[k], n5[dx].x, yc[k] * n5[dx].y);
                    float u   = fmaf(th, dot, dot);      // (1+tanh)*dot
                    xr[k] = fmaf(n5[dx].z, u, xr[k]);
                    yr[k] = fmaf(n5[dx].w, u, yr[k]);
                }
            }
        }
    }
}

// -------------------- ETF iterations 1 & 2 --------------------
// 128-thread blocks: 51 regs/thread -> ~10 blocks/SM resident (vs 4 with 256),
// better barrier/load-phase overlap and smaller tail quantum.
__global__ void __launch_bounds__(128) k_iter(int sel) {
    __shared__ float4 sN[HHALO][HW];
    __shared__ float  sG[HHALO][HW];

    int c = blockIdx.z;
    const float* gm = g_gmag + c * NPIX;
    const float* xi = (sel ? g_xnB : g_xnA) + c * NPIX;
    const float* yi = (sel ? g_ynB : g_ynA) + c * NPIX;
    float* xo = (sel ? g_xnA : g_xnB) + c * NPIX;
    float* yo = (sel ? g_ynA : g_ynB) + c * NPIX;

    float ginv = 1.0f / __int_as_float(g_gmax[c]);
    int bx0 = blockIdx.x * TW - 2;
    int by0 = blockIdx.y * TH - 2;
    int tid = threadIdx.y * 32 + threadIdx.x;

    load_tile(sN, sG, gm, xi, yi, ginv, bx0, by0, tid);
    __syncthreads();

    int tx = threadIdx.x;
    int row0 = threadIdx.y * 4;
    int px = blockIdx.x * TW + tx;
    float xr[4], yr[4];
    etf_core(sN, sG, tx, row0, xr, yr);

#pragma unroll
    for (int k = 0; k < 4; k++) {
        float invm = rsqrtf(fmaf(xr[k], xr[k], yr[k] * yr[k]));
        int o = (blockIdx.y * TH + row0 + k) * WW + px;
        xo[o] = xr[k] * invm;
        yo[o] = yr[k] * invm;
    }
}

// -------------------- ETF iteration 3 fused with angle + stats --------------------
// Reduction: fp32 warp-level shuffles only (|a|<=90), then one fp64 no-return
// atomic per warp per counter. No smem stage, no trailing __syncthreads.
__global__ void __launch_bounds__(128) k_iter3(float* __restrict__ out) {
    __shared__ float4 sN[HHALO][HW];
    __shared__ float  sG[HHALO][HW];

    int c = blockIdx.z;
    const float* gm = g_gmag + c * NPIX;
    const float* xi = g_xnA + c * NPIX;   // iter1: A->B, iter2: B->A, iter3 reads A
    const float* yi = g_ynA + c * NPIX;

    float ginv = 1.0f / __int_as_float(g_gmax[c]);
    int bx0 = blockIdx.x * TW - 2;
    int by0 = blockIdx.y * TH - 2;
    int tid = threadIdx.y * 32 + threadIdx.x;

    load_tile(sN, sG, gm, xi, yi, ginv, bx0, by0, tid);
    __syncthreads();

    int tx = threadIdx.x;
    int row0 = threadIdx.y * 4;
    int px = blockIdx.x * TW + tx;
    float xr[4], yr[4];
    etf_core(sN, sG, tx, row0, xr, yr);

    float s = 0.f, s2 = 0.f;
#pragma unroll
    for (int k = 0; k < 4; k++) {
        // normalization cancels inside atan(-y/x); divide directly
        float t = __fdividef(-yr[k], xr[k]);
        float a = atan_fast(t) * 57.2957795131f;  // 180/pi
        int o = c * NPIX + (blockIdx.y * TH + row0 + k) * WW + px;
        out[o] = a;
        s += a;
        s2 = fmaf(a, a, s2);
    }

#pragma unroll
    for (int off = 16; off; off >>= 1) {
        s  += __shfl_xor_sync(0xffffffffu, s, off);
        s2 += __shfl_xor_sync(0xffffffffu, s2, off);
    }
    if ((tid & 31) == 0) {
        atomicAdd(&g_sum[c], (double)s);     // return unused -> REDG
        atomicAdd(&g_sumsq[c], (double)s2);
    }
}

// -------------------- normalize (float4) + recycle state --------------------
__global__ void k_norm(float* __restrict__ out) {
    __shared__ float smu, sinv;
    int c = blockIdx.y;
    if (threadIdx.x == 0) {
        double mean = g_sum[c] / (double)NPIX;
        double var  = g_sumsq[c] / (double)NPIX - mean * mean;
        smu  = (float)mean;
        sinv = (float)(1.0 / sqrt(var + 1e-5));
        if (blockIdx.x == 0) g_gmax[c] = 0;   // recycle for next replay
    }
    __syncthreads();
    float4* o4 = (float4*)(out + c * NPIX);
    int i = blockIdx.x * blockDim.x + threadIdx.x;
    float4 v = o4[i];
    float mu = smu, is = sinv;
    v.x = (v.x - mu) * is;
    v.y = (v.y - mu) * is;
    v.z = (v.z - mu) * is;
    v.w = (v.w - mu) * is;
    o4[i] = v;
}

extern "C" void kernel_launch(void* const* d_in, const int* in_sizes, int n_in,
                              void* d_out, int out_size) {
    const float* img = (const float*)d_in[0];
    float* out = (float*)d_out;

    k_sobel<<<dim3(WW / 32, HH / 8, BC), dim3(32, 8)>>>(img);
    k_iter<<<dim3(WW / TW, HH / TH, BC), dim3(32, 4)>>>(0);   // A -> B
    k_iter<<<dim3(WW / TW, HH / TH, BC), dim3(32, 4)>>>(1);   // B -> A
    k_iter3<<<dim3(WW / TW, HH / TH, BC), dim3(32, 4)>>>(out);// A -> out (+stats)
    k_norm<<<dim3(NPIX / 4 / 256, BC), 256>>>(out);
}